// round 14
// baseline (speedup 1.0000x reference)
#include <cuda_runtime.h>
#include <cstdint>

// Problem constants
#define BATCH   2048
#define NTOK    64
#define DIM     512
#define NH      16
#define HD      32
#define MROWS   (BATCH * NTOK)      // 131072
#define QKVCOLS (3 * DIM)           // 1536
#define SCALE   0.17677669529663687f // 32^-0.5

// Scratch (allocation-free: __device__ globals)
__device__ float g_qkv[(size_t)MROWS * QKVCOLS];   // [B*N, 1536] rounded, Q pre-scaled, NORMAL layout
__device__ float g_attn[(size_t)MROWS * DIM];      // [B*N, 512] tf32-rounded, PERM16 k-layout
__device__ float g_xr[(size_t)MROWS * DIM];        // tf32-rounded x (PERM16)
__device__ float g_wqkv[(size_t)QKVCOLS * DIM];    // tf32-rounded W_qkv (PERM16)
__device__ float g_wproj[(size_t)DIM * DIM];       // tf32-rounded W_proj (PERM16)
__device__ float g_bias[NH * NTOK * NTOK];         // expanded rel-pos bias

__device__ __forceinline__ float tf32r(float x) {
    float y;
    asm("cvt.rna.tf32.f32 %0, %1;" : "=f"(y) : "f"(x));
    return y;
}

__device__ __forceinline__ uint32_t smem_u32(const void* p) {
    uint32_t a;
    asm("{ .reg .u64 t; cvta.to.shared.u64 t, %1; cvt.u32.u64 %0, t; }" : "=r"(a) : "l"(p));
    return a;
}

__device__ __forceinline__ void cp16(uint32_t s, const void* g) {
    asm volatile("cp.async.cg.shared.global [%0], [%1], 16;" :: "r"(s), "l"(g));
}

__device__ __forceinline__ void mma_tf32(float* d, const uint32_t* a, const uint32_t* b) {
    asm volatile(
        "mma.sync.aligned.m16n8k8.row.col.f32.tf32.tf32.f32 "
        "{%0,%1,%2,%3}, {%4,%5,%6,%7}, {%8,%9}, {%0,%1,%2,%3};"
        : "+f"(d[0]), "+f"(d[1]), "+f"(d[2]), "+f"(d[3])
        : "r"(a[0]), "r"(a[1]), "r"(a[2]), "r"(a[3]), "r"(b[0]), "r"(b[1]));
}

// ---------------------------------------------------------------------------
// Round + 16-wide k-permute: within each 16-group, pos(k) = (k&3)*4 + (k>>2).
// Order: k0,k4,k8,k12, k1,k5,k9,k13, k2,k6,k10,k14, k3,k7,k11,k15.
// One thread = 16 floats = 4x4 register transpose.
// ---------------------------------------------------------------------------
__global__ void __launch_bounds__(256) roundperm16(const float4* __restrict__ in,
                                                   float4* __restrict__ out, int n16) {
    int i = blockIdx.x * blockDim.x + threadIdx.x;
    if (i < n16) {
        float4 a0 = in[4 * i + 0];   // k0..k3
        float4 a1 = in[4 * i + 1];   // k4..k7
        float4 a2 = in[4 * i + 2];   // k8..k11
        float4 a3 = in[4 * i + 3];   // k12..k15
        float4 o0, o1, o2, o3;
        o0.x = tf32r(a0.x); o0.y = tf32r(a1.x); o0.z = tf32r(a2.x); o0.w = tf32r(a3.x);
        o1.x = tf32r(a0.y); o1.y = tf32r(a1.y); o1.z = tf32r(a2.y); o1.w = tf32r(a3.y);
        o2.x = tf32r(a0.z); o2.y = tf32r(a1.z); o2.z = tf32r(a2.z); o2.w = tf32r(a3.z);
        o3.x = tf32r(a0.w); o3.y = tf32r(a1.w); o3.z = tf32r(a2.w); o3.w = tf32r(a3.w);
        out[4 * i + 0] = o0;
        out[4 * i + 1] = o1;
        out[4 * i + 2] = o2;
        out[4 * i + 3] = o3;
    }
}

// ---------------------------------------------------------------------------
// Expand Swin rel-pos bias table -> g_bias[h][row][col]
// ---------------------------------------------------------------------------
__global__ void __launch_bounds__(256) bias_expand(const float* __restrict__ btab,
                                                   float* __restrict__ gb) {
    int i = blockIdx.x * 256 + threadIdx.x;
    int h = i >> 12;
    int rc = i & 4095;
    int row = rc >> 6, col = rc & 63;
    int yi = row >> 3, xi = row & 7;
    int yj = col >> 3, xj = col & 7;
    int idx = (yi - yj + 7) * 15 + (xi - xj + 7);
    gb[i] = btab[idx * NH + h];
}

// ---------------------------------------------------------------------------
// GEMM on PERM16 operands: C = A @ W^T + bias (C in NORMAL layout).
// 128x128x32, 256 thr (8 warps 2x4), warp tile 64x32.
// float4 fragment units: unit (4g+c) of a row holds pairs (c,c+4) for
// k8-groups 2g (.x,.y) and 2g+1 (.z,.w). XOR swizzle at unit granularity:
//   u' = u ^ ((row&1)<<2)   (cp.async chunk: cb' = cb ^ ((row&1)<<2))
// Store phase: 8 lanes = 1 row, permutation -> conflict-free.
// Frag phase: rows r,r+1 map unit-quad onto complementary halves -> 8
// distinct chunks -> conflict-free LDS.128 (24/thread-ktile, was 48 LDS.64).
// Stage = 32KB, STAGES=3, 2 CTAs/SM, exact tail wait.
// MODE 0: plain fp32 store. MODE 1: qkv — tf32-round + pre-scale Q cols.
// ---------------------------------------------------------------------------
#define BM 128
#define BN 128
#define BK 32
#define ROWF4 8                           // float4 units per 128B row
#define STG_A 16384                       // 128 rows x 128B
#define STG 32768                         // A + B per stage
#define STAGES 3
#define GSMEM (STAGES * STG)              // 98304 B

template<int MODE>
__global__ void __launch_bounds__(256, 2) gemm_hmma(
    const float* __restrict__ A, const float* __restrict__ W,
    const float* __restrict__ bias, float* __restrict__ C,
    int N, int K)
{
    extern __shared__ float smem[];
    const uint32_t sb = smem_u32(smem);
    const int tid  = threadIdx.x;
    const int lane = tid & 31;
    const int warp = tid >> 5;
    const int wm   = warp >> 2;
    const int wn   = warp & 3;
    const int mb   = blockIdx.y * BM;
    const int nb   = blockIdx.x * BN;

    // cp.async mapping: rows jr (+32p), 16B chunk cb, swizzled chunk
    const int jr = tid >> 3;
    const int cb = tid & 7;
    const int cbs = cb ^ ((jr & 1) << 2);          // per-thread const
    const float* Ag = A + (size_t)(mb + jr) * K + cb * 4;
    const float* Wg = W + (size_t)(nb + jr) * K + cb * 4;
    const uint32_t soff = (uint32_t)(jr * 128 + cbs * 16);

    #pragma unroll
    for (int s = 0; s < STAGES; s++) {
        const uint32_t b = sb + s * STG;
        #pragma unroll
        for (int p = 0; p < 4; p++)
            cp16(b + soff + p * 32 * 128, Ag + s * BK + (size_t)p * 32 * K);
        #pragma unroll
        for (int p = 0; p < 4; p++)
            cp16(b + STG_A + soff + p * 32 * 128, Wg + s * BK + (size_t)p * 32 * K);
        asm volatile("cp.async.commit_group;" ::: "memory");
    }

    float acc[4][4][4] = {};
    const int KT = K / BK;
    const int fr  = lane >> 2;             // fragment row within 8
    const int swz = (fr & 1) << 2;         // unit-level XOR (per-thread const)
    const int ub  = lane & 3;              // unit within group quad
    const int fc2 = ub * 2;                // C-fragment col pair base

    for (int kt = 0; kt < KT; kt++) {
        const int rem = KT - 1 - kt;
        if (rem >= STAGES - 1)
            asm volatile("cp.async.wait_group %0;" :: "n"(STAGES - 1) : "memory");
        else if (rem == 1)
            asm volatile("cp.async.wait_group 1;" ::: "memory");
        else
            asm volatile("cp.async.wait_group 0;" ::: "memory");
        __syncthreads();

        const int buf = kt % STAGES;
        const float4* Ab4 = (const float4*)(smem + buf * (STG / 4)) + (wm * 64) * ROWF4;
        const float4* Bb4 = (const float4*)(smem + buf * (STG / 4) + (STG_A / 4)) + (wn * 32) * ROWF4;

        #pragma unroll
        for (int g = 0; g < 2; g++) {          // two 16-float groups per ktile
            const int up = (g * 4 + ub) ^ swz;
            float4 av0[4], av1[4], bv[4];
            #pragma unroll
            for (int mi = 0; mi < 4; mi++) {
                av0[mi] = Ab4[(mi * 16 + fr) * ROWF4 + up];
                av1[mi] = Ab4[(mi * 16 + fr + 8) * ROWF4 + up];
            }
            #pragma unroll
            for (int ni = 0; ni < 4; ni++)
                bv[ni] = Bb4[(ni * 8 + fr) * ROWF4 + up];

            #pragma unroll
            for (int mi = 0; mi < 4; mi++) {
                uint32_t ae[4], ao[4];
                ae[0] = __float_as_uint(av0[mi].x); ae[1] = __float_as_uint(av1[mi].x);
                ae[2] = __float_as_uint(av0[mi].y); ae[3] = __float_as_uint(av1[mi].y);
                ao[0] = __float_as_uint(av0[mi].z); ao[1] = __float_as_uint(av1[mi].z);
                ao[2] = __float_as_uint(av0[mi].w); ao[3] = __float_as_uint(av1[mi].w);
                #pragma unroll
                for (int ni = 0; ni < 4; ni++) {
                    uint32_t be[2], bo[2];
                    be[0] = __float_as_uint(bv[ni].x); be[1] = __float_as_uint(bv[ni].y);
                    bo[0] = __float_as_uint(bv[ni].z); bo[1] = __float_as_uint(bv[ni].w);
                    mma_tf32(acc[mi][ni], ae, be);     // ks = 2g
                    mma_tf32(acc[mi][ni], ao, bo);     // ks = 2g+1
                }
            }
        }
        __syncthreads();   // all reads of buf complete before refill

        const int nk = kt + STAGES;
        if (nk < KT) {
            const uint32_t b = sb + buf * STG;     // nk % STAGES == buf
            #pragma unroll
            for (int p = 0; p < 4; p++)
                cp16(b + soff + p * 32 * 128, Ag + nk * BK + (size_t)p * 32 * K);
            #pragma unroll
            for (int p = 0; p < 4; p++)
                cp16(b + STG_A + soff + p * 32 * 128, Wg + nk * BK + (size_t)p * 32 * K);
            asm volatile("cp.async.commit_group;" ::: "memory");
        }
    }

    #pragma unroll
    for (int mi = 0; mi < 4; mi++) {
        const int row = mb + wm * 64 + mi * 16 + fr;
        #pragma unroll
        for (int ni = 0; ni < 4; ni++) {
            const int col = nb + wn * 32 + ni * 8 + fc2;
            const float b0 = __ldg(bias + col), b1 = __ldg(bias + col + 1);
            float* Cp = C + (size_t)row * N + col;
            float v0 = acc[mi][ni][0] + b0, v1 = acc[mi][ni][1] + b1;
            float v2 = acc[mi][ni][2] + b0, v3 = acc[mi][ni][3] + b1;
            if (MODE == 1) {
                const float s = (col < DIM) ? SCALE : 1.0f;   // Q pre-scale
                v0 = tf32r(v0 * s); v1 = tf32r(v1 * s);
                v2 = tf32r(v2 * s); v3 = tf32r(v3 * s);
            }
            *(float2*)Cp = make_float2(v0, v1);
            *(float2*)(Cp + (size_t)8 * N) = make_float2(v2, v3);
        }
    }
}

// ---------------------------------------------------------------------------
// Attention (R8 core): one (b,h) per block, 128 threads, pure cp.async loads,
// V in [m][40], register softmax, P aliases Qs/Ks.
// Output stores PERM16 (feeds proj GEMM's LDS.128 fragment path).
// ---------------------------------------------------------------------------
#define QK_ROWB 144                       // 36 floats
#define V_ROWB  160                       // 40 floats

__global__ void __launch_bounds__(128, 6) attn_kernel(
    const float* __restrict__ qkv, const float* __restrict__ gbias,
    float* __restrict__ out)
{
    __shared__ float sm[2 * 64 * 36];          // Qs | Ks; later aliased by P
    __shared__ float Vs[64][40];
    float (*Qs)[36] = (float(*)[36])sm;
    float (*Ks)[36] = (float(*)[36])(sm + 64 * 36);
    float (*P)[68]  = (float(*)[68])sm;

    const int bh = blockIdx.x;
    const int b = bh >> 4;
    const int h = bh & 15;
    const int tid = threadIdx.x;
    const int lane = tid & 31;
    const int warp = tid >> 5;

    const float* base = qkv + (size_t)b * NTOK * QKVCOLS + h * HD;
    const uint32_t sq = smem_u32(sm);
    const uint32_t sv = smem_u32(Vs);

    #pragma unroll
    for (int p = 0; p < 4; p++) {
        const int t = tid + p * 128;
        const int row = t >> 3, c = t & 7;
        const float* g = base + (size_t)row * QKVCOLS + c * 4;
        cp16(sq + row * QK_ROWB + c * 16, g);                        // Q
        cp16(sq + 64 * QK_ROWB + row * QK_ROWB + c * 16, g + DIM);   // K
        cp16(sv + row * V_ROWB + c * 16, g + 2 * DIM);               // V
    }
    asm volatile("cp.async.commit_group;" ::: "memory");
    asm volatile("cp.async.wait_group 0;" ::: "memory");
    __syncthreads();

    float sacc[8][4] = {};
    #pragma unroll
    for (int ks = 0; ks < 4; ks++) {
        const int k8 = ks * 8;
        uint32_t af[4];
        const float* p = &Qs[warp * 16 + (lane >> 2)][k8 + (lane & 3)];
        af[0] = __float_as_uint(p[0]);
        af[1] = __float_as_uint(p[8 * 36]);
        af[2] = __float_as_uint(p[4]);
        af[3] = __float_as_uint(p[8 * 36 + 4]);
        #pragma unroll
        for (int ni = 0; ni < 8; ni++) {
            uint32_t bf[2];
            const float* q = &Ks[ni * 8 + (lane >> 2)][k8 + (lane & 3)];
            bf[0] = __float_as_uint(q[0]);
            bf[1] = __float_as_uint(q[4]);
            mma_tf32(sacc[ni], af, bf);
        }
    }

    const int rA = warp * 16 + (lane >> 2);
    const int c0 = (lane & 3) * 2;
    {
        const float* gb = gbias + h * (NTOK * NTOK);
        #pragma unroll
        for (int ni = 0; ni < 8; ni++) {
            const int col = ni * 8 + c0;
            float2 b0 = *(const float2*)(gb + rA * 64 + col);
            float2 b1 = *(const float2*)(gb + (rA + 8) * 64 + col);
            sacc[ni][0] += b0.x; sacc[ni][1] += b0.y;
            sacc[ni][2] += b1.x; sacc[ni][3] += b1.y;
        }
    }
    float mx0 = -1e30f, mx1 = -1e30f;
    #pragma unroll
    for (int ni = 0; ni < 8; ni++) {
        mx0 = fmaxf(mx0, fmaxf(sacc[ni][0], sacc[ni][1]));
        mx1 = fmaxf(mx1, fmaxf(sacc[ni][2], sacc[ni][3]));
    }
    mx0 = fmaxf(mx0, __shfl_xor_sync(0xffffffffu, mx0, 1));
    mx0 = fmaxf(mx0, __shfl_xor_sync(0xffffffffu, mx0, 2));
    mx1 = fmaxf(mx1, __shfl_xor_sync(0xffffffffu, mx1, 1));
    mx1 = fmaxf(mx1, __shfl_xor_sync(0xffffffffu, mx1, 2));

    float sum0 = 0.f, sum1 = 0.f;
    #pragma unroll
    for (int ni = 0; ni < 8; ni++) {
        sacc[ni][0] = __expf(sacc[ni][0] - mx0);
        sacc[ni][1] = __expf(sacc[ni][1] - mx0);
        sacc[ni][2] = __expf(sacc[ni][2] - mx1);
        sacc[ni][3] = __expf(sacc[ni][3] - mx1);
        sum0 += sacc[ni][0] + sacc[ni][1];
        sum1 += sacc[ni][2] + sacc[ni][3];
    }
    sum0 += __shfl_xor_sync(0xffffffffu, sum0, 1);
    sum0 += __shfl_xor_sync(0xffffffffu, sum0, 2);
    sum1 += __shfl_xor_sync(0xffffffffu, sum1, 1);
    sum1 += __shfl_xor_sync(0xffffffffu, sum1, 2);
    const float inv0 = 1.f / sum0, inv1 = 1.f / sum1;

    __syncthreads();

    #pragma unroll
    for (int ni = 0; ni < 8; ni++) {
        const int col = ni * 8 + c0;
        *(float2*)(&P[rA][col]) =
            make_float2(tf32r(sacc[ni][0] * inv0), tf32r(sacc[ni][1] * inv0));
        *(float2*)(&P[rA + 8][col]) =
            make_float2(tf32r(sacc[ni][2] * inv1), tf32r(sacc[ni][3] * inv1));
    }
    __syncthreads();

    float oacc[4][4] = {};
    #pragma unroll
    for (int ks = 0; ks < 8; ks++) {
        const int k8 = ks * 8;
        uint32_t af[4];
        const float* p = &P[warp * 16 + (lane >> 2)][k8 + (lane & 3)];
        af[0] = __float_as_uint(p[0]);
        af[1] = __float_as_uint(p[8 * 68]);
        af[2] = __float_as_uint(p[4]);
        af[3] = __float_as_uint(p[8 * 68 + 4]);
        #pragma unroll
        for (int ni = 0; ni < 4; ni++) {
            uint32_t bf[2];
            const float* q = &Vs[k8 + (lane & 3)][ni * 8 + (lane >> 2)];
            bf[0] = __float_as_uint(q[0]);
            bf[1] = __float_as_uint(q[4 * 40]);
            mma_tf32(oacc[ni], af, bf);
        }
    }
    {
        // PERM16 stores: col -> grp*16 + (k16&3)*4 + (k16>>2)
        float* ob = out + (size_t)b * NTOK * DIM + h * HD;
        #pragma unroll
        for (int ni = 0; ni < 4; ni++) {
            const int cbse = ni * 8;
            const int colA = cbse + c0, colB = cbse + c0 + 1;
            const int kA = colA & 15, kB = colB & 15;
            const int pA = (colA & ~15) + (kA & 3) * 4 + (kA >> 2);
            const int pB = (colB & ~15) + (kB & 3) * 4 + (kB >> 2);
            ob[(size_t)rA * DIM + pA] = tf32r(oacc[ni][0]);
            ob[(size_t)rA * DIM + pB] = tf32r(oacc[ni][1]);
            ob[(size_t)(rA + 8) * DIM + pA] = tf32r(oacc[ni][2]);
            ob[(size_t)(rA + 8) * DIM + pB] = tf32r(oacc[ni][3]);
        }
    }
}

// ---------------------------------------------------------------------------
extern "C" void kernel_launch(void* const* d_in, const int* in_sizes, int n_in,
                              void* d_out, int out_size)
{
    const float* x     = (const float*)d_in[0];
    const float* Wqkv  = (const float*)d_in[1];
    const float* bqkv  = (const float*)d_in[2];
    const float* Wproj = (const float*)d_in[3];
    const float* bproj = (const float*)d_in[4];
    const float* btab  = (const float*)d_in[5];
    float* out = (float*)d_out;

    float *qkvbuf, *attnbuf, *xr, *wqkvr, *wprojr, *gbias;
    cudaGetSymbolAddress((void**)&qkvbuf, g_qkv);
    cudaGetSymbolAddress((void**)&attnbuf, g_attn);
    cudaGetSymbolAddress((void**)&xr, g_xr);
    cudaGetSymbolAddress((void**)&wqkvr, g_wqkv);
    cudaGetSymbolAddress((void**)&wprojr, g_wproj);
    cudaGetSymbolAddress((void**)&gbias, g_bias);

    cudaFuncSetAttribute(gemm_hmma<1>, cudaFuncAttributeMaxDynamicSharedMemorySize, GSMEM);
    cudaFuncSetAttribute(gemm_hmma<0>, cudaFuncAttributeMaxDynamicSharedMemorySize, GSMEM);

    // 0) round + 16-wide k-permute x and weights; expand bias table
    {
        int n16 = MROWS * DIM / 16;
        roundperm16<<<(n16 + 255) / 256, 256>>>((const float4*)x, (float4*)xr, n16);
        n16 = QKVCOLS * DIM / 16;
        roundperm16<<<(n16 + 255) / 256, 256>>>((const float4*)Wqkv, (float4*)wqkvr, n16);
        n16 = DIM * DIM / 16;
        roundperm16<<<(n16 + 255) / 256, 256>>>((const float4*)Wproj, (float4*)wprojr, n16);
        bias_expand<<<NH * NTOK * NTOK / 256, 256>>>(btab, gbias);
    }

    // 1) QKV projection (PERM16 operands; epilogue rounds + pre-scales Q; normal output)
    gemm_hmma<1><<<dim3(QKVCOLS / BN, MROWS / BM), 256, GSMEM>>>(
        xr, wqkvr, bqkv, qkvbuf, QKVCOLS, DIM);

    // 2) Windowed attention per (b, h); writes PERM16 g_attn
    attn_kernel<<<BATCH * NH, 128>>>(qkvbuf, gbias, attnbuf);

    // 3) Output projection (PERM16 operands; normal output)
    gemm_hmma<0><<<dim3(DIM / BN, MROWS / BM), 256, GSMEM>>>(
        attnbuf, wprojr, bproj, out, DIM, DIM);
}

// round 15
// speedup vs baseline: 1.0726x; 1.0726x over previous
#include <cuda_runtime.h>
#include <cstdint>

// Problem constants
#define BATCH   2048
#define NTOK    64
#define DIM     512
#define NH      16
#define HD      32
#define MROWS   (BATCH * NTOK)      // 131072
#define QKVCOLS (3 * DIM)           // 1536
#define SCALE   0.17677669529663687f // 32^-0.5

// Scratch (allocation-free: __device__ globals)
__device__ float g_qkv[(size_t)MROWS * QKVCOLS];   // [B*N, 1536] rounded, Q pre-scaled, NORMAL layout
__device__ float g_attn[(size_t)MROWS * DIM];      // [B*N, 512] tf32-rounded, PERMUTED k-layout
__device__ float g_xr[(size_t)MROWS * DIM];        // tf32-rounded x (PERMUTED)
__device__ float g_wqkv[(size_t)QKVCOLS * DIM];    // tf32-rounded W_qkv (PERMUTED)
__device__ float g_wproj[(size_t)DIM * DIM];       // tf32-rounded W_proj (PERMUTED)
__device__ float g_bias[NH * NTOK * NTOK];         // expanded rel-pos bias

__device__ __forceinline__ float tf32r(float x) {
    float y;
    asm("cvt.rna.tf32.f32 %0, %1;" : "=f"(y) : "f"(x));
    return y;
}

__device__ __forceinline__ uint32_t smem_u32(const void* p) {
    uint32_t a;
    asm("{ .reg .u64 t; cvta.to.shared.u64 t, %1; cvt.u32.u64 %0, t; }" : "=r"(a) : "l"(p));
    return a;
}

__device__ __forceinline__ void cp16(uint32_t s, const void* g) {
    asm volatile("cp.async.cg.shared.global [%0], [%1], 16;" :: "r"(s), "l"(g));
}

__device__ __forceinline__ void mma_tf32(float* d, const uint32_t* a, const uint32_t* b) {
    asm volatile(
        "mma.sync.aligned.m16n8k8.row.col.f32.tf32.tf32.f32 "
        "{%0,%1,%2,%3}, {%4,%5,%6,%7}, {%8,%9}, {%0,%1,%2,%3};"
        : "+f"(d[0]), "+f"(d[1]), "+f"(d[2]), "+f"(d[3])
        : "r"(a[0]), "r"(a[1]), "r"(a[2]), "r"(a[3]), "r"(b[0]), "r"(b[1]));
}

// ---------------------------------------------------------------------------
// Round + k-permute pass: 8 floats per thread.
// Permuted position order within each 8-group: (k0,k4,k1,k5,k2,k6,k3,k7),
// i.e. pos(k) = 2k for k<4, 2(k-4)+1 for k>=4.
// ---------------------------------------------------------------------------
__global__ void __launch_bounds__(256) roundperm8(const float4* __restrict__ in,
                                                  float4* __restrict__ out, int n8) {
    int i = blockIdx.x * blockDim.x + threadIdx.x;
    if (i < n8) {
        float4 a = in[2 * i];          // k0..k3
        float4 b = in[2 * i + 1];      // k4..k7
        float4 o0, o1;
        o0.x = tf32r(a.x); o0.y = tf32r(b.x); o0.z = tf32r(a.y); o0.w = tf32r(b.y);
        o1.x = tf32r(a.z); o1.y = tf32r(b.z); o1.z = tf32r(a.w); o1.w = tf32r(b.w);
        out[2 * i]     = o0;
        out[2 * i + 1] = o1;
    }
}

// ---------------------------------------------------------------------------
// Expand Swin rel-pos bias table -> g_bias[h][row][col]
// ---------------------------------------------------------------------------
__global__ void __launch_bounds__(256) bias_expand(const float* __restrict__ btab,
                                                   float* __restrict__ gb) {
    int i = blockIdx.x * 256 + threadIdx.x;
    int h = i >> 12;
    int rc = i & 4095;
    int row = rc >> 6, col = rc & 63;
    int yi = row >> 3, xi = row & 7;
    int yj = col >> 3, xj = col & 7;
    int idx = (yi - yj + 7) * 15 + (xi - xj + 7);
    gb[i] = btab[idx * NH + h];
}

// ---------------------------------------------------------------------------
// GEMM on k-PERMUTED operands (R13 layout): C = A @ W^T + bias.
// 128x128x32, 256 thr (8 warps 2x4), warp tile 64x32.
// XOR-swizzled smem, 128B rows: u' = u ^ ((row&3)<<2) at float2 granularity
// -> conflict-free STS.128 and LDS.64 fragment loads.
// NEW vs R13: ONE barrier per ktile — prefetch distance 2, tile kt+2 goes to
// slot (kt+2)%3 (last read at iter kt-1, protected by this iter's barrier).
// Exact tail wait: youngest committed group at iter kt is kt+1, so
// wait_group(1) suffices except kt=KT-1 -> wait_group(0).
// Stage = 32KB, STAGES=3, 2 CTAs/SM.
// MODE 0: plain fp32 store. MODE 1: qkv — tf32-round + pre-scale Q cols.
// ---------------------------------------------------------------------------
#define BM 128
#define BN 128
#define BK 32
#define ROWF2 16                          // float2 units per 128B row
#define STG_A 16384                       // 128 rows x 128B
#define STG 32768                         // A + B per stage
#define STAGES 3
#define GSMEM (STAGES * STG)              // 98304 B

template<int MODE>
__global__ void __launch_bounds__(256, 2) gemm_hmma(
    const float* __restrict__ A, const float* __restrict__ W,
    const float* __restrict__ bias, float* __restrict__ C,
    int N, int K)
{
    extern __shared__ float smem[];
    const uint32_t sb = smem_u32(smem);
    const int tid  = threadIdx.x;
    const int lane = tid & 31;
    const int warp = tid >> 5;
    const int wm   = warp >> 2;
    const int wn   = warp & 3;
    const int mb   = blockIdx.y * BM;
    const int nb   = blockIdx.x * BN;

    // cp.async mapping: rows jr (+32p), 16B chunk cb, swizzled chunk
    const int jr = tid >> 3;
    const int cb = tid & 7;
    const int cbs = cb ^ ((jr & 3) << 1);          // per-thread const
    const float* Ag = A + (size_t)(mb + jr) * K + cb * 4;
    const float* Wg = W + (size_t)(nb + jr) * K + cb * 4;
    const uint32_t soff = (uint32_t)(jr * 128 + cbs * 16);

    // prologue: tiles 0,1 -> slots 0,1 (prefetch distance 2)
    #pragma unroll
    for (int s = 0; s < 2; s++) {
        const uint32_t b = sb + s * STG;
        #pragma unroll
        for (int p = 0; p < 4; p++)
            cp16(b + soff + p * 32 * 128, Ag + s * BK + (size_t)p * 32 * K);
        #pragma unroll
        for (int p = 0; p < 4; p++)
            cp16(b + STG_A + soff + p * 32 * 128, Wg + s * BK + (size_t)p * 32 * K);
        asm volatile("cp.async.commit_group;" ::: "memory");
    }

    float acc[4][4][4] = {};
    const int KT = K / BK;
    const int fr  = lane >> 2;             // fragment row within 8
    const int swz = (fr & 3) << 2;         // per-thread XOR for float2 units
    const int ub  = lane & 3;              // base float2 unit within k8 group
    const int fc2 = ub * 2;                // logical col pair base (epilogue)

    for (int kt = 0; kt < KT; kt++) {
        // youngest committed group is kt+1 (when it exists)
        if (kt + 1 < KT)
            asm volatile("cp.async.wait_group 1;" ::: "memory");
        else
            asm volatile("cp.async.wait_group 0;" ::: "memory");
        __syncthreads();   // tile kt ready for all; all warps done with iter kt-1

        // prefetch tile kt+2 into slot (kt+2)%3 (last read at iter kt-1)
        const int nk = kt + 2;
        if (nk < KT) {
            const uint32_t b = sb + (nk % STAGES) * STG;
            #pragma unroll
            for (int p = 0; p < 4; p++)
                cp16(b + soff + p * 32 * 128, Ag + nk * BK + (size_t)p * 32 * K);
            #pragma unroll
            for (int p = 0; p < 4; p++)
                cp16(b + STG_A + soff + p * 32 * 128, Wg + nk * BK + (size_t)p * 32 * K);
            asm volatile("cp.async.commit_group;" ::: "memory");
        }

        const int buf = kt % STAGES;
        const float2* Ab2 = (const float2*)(smem + buf * (STG / 4)) + (wm * 64) * ROWF2;
        const float2* Bb2 = (const float2*)(smem + buf * (STG / 4) + (STG_A / 4)) + (wn * 32) * ROWF2;

        #pragma unroll
        for (int ks = 0; ks < 4; ks++) {
            const int up = (ks * 4 + ub) ^ swz;    // swizzled float2 unit
            uint32_t afr[4][4], bfr[4][2];
            #pragma unroll
            for (int mi = 0; mi < 4; mi++) {
                float2 v0 = Ab2[(mi * 16 + fr) * ROWF2 + up];
                float2 v1 = Ab2[(mi * 16 + fr + 8) * ROWF2 + up];
                afr[mi][0] = __float_as_uint(v0.x);
                afr[mi][1] = __float_as_uint(v1.x);
                afr[mi][2] = __float_as_uint(v0.y);
                afr[mi][3] = __float_as_uint(v1.y);
            }
            #pragma unroll
            for (int ni = 0; ni < 4; ni++) {
                float2 w = Bb2[(ni * 8 + fr) * ROWF2 + up];
                bfr[ni][0] = __float_as_uint(w.x);
                bfr[ni][1] = __float_as_uint(w.y);
            }
            #pragma unroll
            for (int mi = 0; mi < 4; mi++)
                #pragma unroll
                for (int ni = 0; ni < 4; ni++)
                    mma_tf32(acc[mi][ni], afr[mi], bfr[ni]);
        }
    }

    #pragma unroll
    for (int mi = 0; mi < 4; mi++) {
        const int row = mb + wm * 64 + mi * 16 + fr;
        #pragma unroll
        for (int ni = 0; ni < 4; ni++) {
            const int col = nb + wn * 32 + ni * 8 + fc2;
            const float b0 = __ldg(bias + col), b1 = __ldg(bias + col + 1);
            float* Cp = C + (size_t)row * N + col;
            float v0 = acc[mi][ni][0] + b0, v1 = acc[mi][ni][1] + b1;
            float v2 = acc[mi][ni][2] + b0, v3 = acc[mi][ni][3] + b1;
            if (MODE == 1) {
                const float s = (col < DIM) ? SCALE : 1.0f;   // Q pre-scale
                v0 = tf32r(v0 * s); v1 = tf32r(v1 * s);
                v2 = tf32r(v2 * s); v3 = tf32r(v3 * s);
            }
            *(float2*)Cp = make_float2(v0, v1);
            *(float2*)(Cp + (size_t)8 * N) = make_float2(v2, v3);
        }
    }
}

// ---------------------------------------------------------------------------
// Attention (R8 core): one (b,h) per block, 128 threads, pure cp.async loads,
// V in [m][40], register softmax, P aliases Qs/Ks.
// Output stores k-PERMUTED (feeds proj GEMM's LDS.64 fragment path).
// ---------------------------------------------------------------------------
#define QK_ROWB 144                       // 36 floats
#define V_ROWB  160                       // 40 floats

__global__ void __launch_bounds__(128, 6) attn_kernel(
    const float* __restrict__ qkv, const float* __restrict__ gbias,
    float* __restrict__ out)
{
    __shared__ float sm[2 * 64 * 36];          // Qs | Ks; later aliased by P
    __shared__ float Vs[64][40];
    float (*Qs)[36] = (float(*)[36])sm;
    float (*Ks)[36] = (float(*)[36])(sm + 64 * 36);
    float (*P)[68]  = (float(*)[68])sm;

    const int bh = blockIdx.x;
    const int b = bh >> 4;
    const int h = bh & 15;
    const int tid = threadIdx.x;
    const int lane = tid & 31;
    const int warp = tid >> 5;

    const float* base = qkv + (size_t)b * NTOK * QKVCOLS + h * HD;
    const uint32_t sq = smem_u32(sm);
    const uint32_t sv = smem_u32(Vs);

    #pragma unroll
    for (int p = 0; p < 4; p++) {
        const int t = tid + p * 128;
        const int row = t >> 3, c = t & 7;
        const float* g = base + (size_t)row * QKVCOLS + c * 4;
        cp16(sq + row * QK_ROWB + c * 16, g);                        // Q
        cp16(sq + 64 * QK_ROWB + row * QK_ROWB + c * 16, g + DIM);   // K
        cp16(sv + row * V_ROWB + c * 16, g + 2 * DIM);               // V
    }
    asm volatile("cp.async.commit_group;" ::: "memory");
    asm volatile("cp.async.wait_group 0;" ::: "memory");
    __syncthreads();

    float sacc[8][4] = {};
    #pragma unroll
    for (int ks = 0; ks < 4; ks++) {
        const int k8 = ks * 8;
        uint32_t af[4];
        const float* p = &Qs[warp * 16 + (lane >> 2)][k8 + (lane & 3)];
        af[0] = __float_as_uint(p[0]);
        af[1] = __float_as_uint(p[8 * 36]);
        af[2] = __float_as_uint(p[4]);
        af[3] = __float_as_uint(p[8 * 36 + 4]);
        #pragma unroll
        for (int ni = 0; ni < 8; ni++) {
            uint32_t bf[2];
            const float* q = &Ks[ni * 8 + (lane >> 2)][k8 + (lane & 3)];
            bf[0] = __float_as_uint(q[0]);
            bf[1] = __float_as_uint(q[4]);
            mma_tf32(sacc[ni], af, bf);
        }
    }

    const int rA = warp * 16 + (lane >> 2);
    const int c0 = (lane & 3) * 2;
    {
        const float* gb = gbias + h * (NTOK * NTOK);
        #pragma unroll
        for (int ni = 0; ni < 8; ni++) {
            const int col = ni * 8 + c0;
            float2 b0 = *(const float2*)(gb + rA * 64 + col);
            float2 b1 = *(const float2*)(gb + (rA + 8) * 64 + col);
            sacc[ni][0] += b0.x; sacc[ni][1] += b0.y;
            sacc[ni][2] += b1.x; sacc[ni][3] += b1.y;
        }
    }
    float mx0 = -1e30f, mx1 = -1e30f;
    #pragma unroll
    for (int ni = 0; ni < 8; ni++) {
        mx0 = fmaxf(mx0, fmaxf(sacc[ni][0], sacc[ni][1]));
        mx1 = fmaxf(mx1, fmaxf(sacc[ni][2], sacc[ni][3]));
    }
    mx0 = fmaxf(mx0, __shfl_xor_sync(0xffffffffu, mx0, 1));
    mx0 = fmaxf(mx0, __shfl_xor_sync(0xffffffffu, mx0, 2));
    mx1 = fmaxf(mx1, __shfl_xor_sync(0xffffffffu, mx1, 1));
    mx1 = fmaxf(mx1, __shfl_xor_sync(0xffffffffu, mx1, 2));

    float sum0 = 0.f, sum1 = 0.f;
    #pragma unroll
    for (int ni = 0; ni < 8; ni++) {
        sacc[ni][0] = __expf(sacc[ni][0] - mx0);
        sacc[ni][1] = __expf(sacc[ni][1] - mx0);
        sacc[ni][2] = __expf(sacc[ni][2] - mx1);
        sacc[ni][3] = __expf(sacc[ni][3] - mx1);
        sum0 += sacc[ni][0] + sacc[ni][1];
        sum1 += sacc[ni][2] + sacc[ni][3];
    }
    sum0 += __shfl_xor_sync(0xffffffffu, sum0, 1);
    sum0 += __shfl_xor_sync(0xffffffffu, sum0, 2);
    sum1 += __shfl_xor_sync(0xffffffffu, sum1, 1);
    sum1 += __shfl_xor_sync(0xffffffffu, sum1, 2);
    const float inv0 = 1.f / sum0, inv1 = 1.f / sum1;

    __syncthreads();

    #pragma unroll
    for (int ni = 0; ni < 8; ni++) {
        const int col = ni * 8 + c0;
        *(float2*)(&P[rA][col]) =
            make_float2(tf32r(sacc[ni][0] * inv0), tf32r(sacc[ni][1] * inv0));
        *(float2*)(&P[rA + 8][col]) =
            make_float2(tf32r(sacc[ni][2] * inv1), tf32r(sacc[ni][3] * inv1));
    }
    __syncthreads();

    float oacc[4][4] = {};
    #pragma unroll
    for (int ks = 0; ks < 8; ks++) {
        const int k8 = ks * 8;
        uint32_t af[4];
        const float* p = &P[warp * 16 + (lane >> 2)][k8 + (lane & 3)];
        af[0] = __float_as_uint(p[0]);
        af[1] = __float_as_uint(p[8 * 68]);
        af[2] = __float_as_uint(p[4]);
        af[3] = __float_as_uint(p[8 * 68 + 4]);
        #pragma unroll
        for (int ni = 0; ni < 4; ni++) {
            uint32_t bf[2];
            const float* q = &Vs[k8 + (lane & 3)][ni * 8 + (lane >> 2)];
            bf[0] = __float_as_uint(q[0]);
            bf[1] = __float_as_uint(q[4 * 40]);
            mma_tf32(oacc[ni], af, bf);
        }
    }
    {
        // k-permuted stores: pos(c)=2c (c<4), 2(c-4)+1 (c>=4)
        const int pos_lo = (c0 < 4) ? (2 * c0) : (2 * (c0 - 4) + 1);
        const int pos_hi = (c0 + 1 < 4) ? (2 * (c0 + 1)) : (2 * (c0 - 3) + 1);
        float* ob = out + (size_t)b * NTOK * DIM + h * HD;
        #pragma unroll
        for (int ni = 0; ni < 4; ni++) {
            const int cbse = ni * 8;
            ob[(size_t)rA * DIM + cbse + pos_lo] = tf32r(oacc[ni][0]);
            ob[(size_t)rA * DIM + cbse + pos_hi] = tf32r(oacc[ni][1]);
            ob[(size_t)(rA + 8) * DIM + cbse + pos_lo] = tf32r(oacc[ni][2]);
            ob[(size_t)(rA + 8) * DIM + cbse + pos_hi] = tf32r(oacc[ni][3]);
        }
    }
}

// ---------------------------------------------------------------------------
extern "C" void kernel_launch(void* const* d_in, const int* in_sizes, int n_in,
                              void* d_out, int out_size)
{
    const float* x     = (const float*)d_in[0];
    const float* Wqkv  = (const float*)d_in[1];
    const float* bqkv  = (const float*)d_in[2];
    const float* Wproj = (const float*)d_in[3];
    const float* bproj = (const float*)d_in[4];
    const float* btab  = (const float*)d_in[5];
    float* out = (float*)d_out;

    float *qkvbuf, *attnbuf, *xr, *wqkvr, *wprojr, *gbias;
    cudaGetSymbolAddress((void**)&qkvbuf, g_qkv);
    cudaGetSymbolAddress((void**)&attnbuf, g_attn);
    cudaGetSymbolAddress((void**)&xr, g_xr);
    cudaGetSymbolAddress((void**)&wqkvr, g_wqkv);
    cudaGetSymbolAddress((void**)&wprojr, g_wproj);
    cudaGetSymbolAddress((void**)&gbias, g_bias);

    cudaFuncSetAttribute(gemm_hmma<1>, cudaFuncAttributeMaxDynamicSharedMemorySize, GSMEM);
    cudaFuncSetAttribute(gemm_hmma<0>, cudaFuncAttributeMaxDynamicSharedMemorySize, GSMEM);

    // 0) round + k-permute x and weights; expand bias table
    {
        int n8 = MROWS * DIM / 8;
        roundperm8<<<(n8 + 255) / 256, 256>>>((const float4*)x, (float4*)xr, n8);
        n8 = QKVCOLS * DIM / 8;
        roundperm8<<<(n8 + 255) / 256, 256>>>((const float4*)Wqkv, (float4*)wqkvr, n8);
        n8 = DIM * DIM / 8;
        roundperm8<<<(n8 + 255) / 256, 256>>>((const float4*)Wproj, (float4*)wprojr, n8);
        bias_expand<<<NH * NTOK * NTOK / 256, 256>>>(btab, gbias);
    }

    // 1) QKV projection (permuted operands; epilogue rounds + pre-scales Q; normal output)
    gemm_hmma<1><<<dim3(QKVCOLS / BN, MROWS / BM), 256, GSMEM>>>(
        xr, wqkvr, bqkv, qkvbuf, QKVCOLS, DIM);

    // 2) Windowed attention per (b, h); writes permuted g_attn
    attn_kernel<<<BATCH * NH, 128>>>(qkvbuf, gbias, attnbuf);

    // 3) Output projection (permuted operands; normal output)
    gemm_hmma<0><<<dim3(DIM / BN, MROWS / BM), 256, GSMEM>>>(
        attnbuf, wprojr, bproj, out, DIM, DIM);
}

// round 16
// speedup vs baseline: 1.0744x; 1.0017x over previous
#include <cuda_runtime.h>
#include <cstdint>

// Problem constants
#define BATCH   2048
#define NTOK    64
#define DIM     512
#define NH      16
#define HD      32
#define MROWS   (BATCH * NTOK)      // 131072
#define QKVCOLS (3 * DIM)           // 1536
#define SCALE   0.17677669529663687f // 32^-0.5

// 8-float group counts for the merged pre-pass
#define NX8   (MROWS * DIM / 8)        // 8388608
#define NW18  (QKVCOLS * DIM / 8)      // 98304
#define NW28  (DIM * DIM / 8)          // 32768
#define NALL8 (NX8 + NW18 + NW28)

// Scratch (allocation-free: __device__ globals)
__device__ float g_qkv[(size_t)MROWS * QKVCOLS];   // [B*N, 1536] rounded, Q pre-scaled, NORMAL layout
__device__ float g_attn[(size_t)MROWS * DIM];      // [B*N, 512] tf32-rounded, PERMUTED k-layout
__device__ float g_xr[(size_t)MROWS * DIM];        // tf32-rounded x (PERMUTED)
__device__ float g_wqkv[(size_t)QKVCOLS * DIM];    // tf32-rounded W_qkv (PERMUTED)
__device__ float g_wproj[(size_t)DIM * DIM];       // tf32-rounded W_proj (PERMUTED)
__device__ float g_bias[NH * NTOK * NTOK];         // expanded rel-pos bias

__device__ __forceinline__ float tf32r(float x) {
    float y;
    asm("cvt.rna.tf32.f32 %0, %1;" : "=f"(y) : "f"(x));
    return y;
}

__device__ __forceinline__ uint32_t smem_u32(const void* p) {
    uint32_t a;
    asm("{ .reg .u64 t; cvta.to.shared.u64 t, %1; cvt.u32.u64 %0, t; }" : "=r"(a) : "l"(p));
    return a;
}

__device__ __forceinline__ void cp16(uint32_t s, const void* g) {
    asm volatile("cp.async.cg.shared.global [%0], [%1], 16;" :: "r"(s), "l"(g));
}

__device__ __forceinline__ void mma_tf32(float* d, const uint32_t* a, const uint32_t* b) {
    asm volatile(
        "mma.sync.aligned.m16n8k8.row.col.f32.tf32.tf32.f32 "
        "{%0,%1,%2,%3}, {%4,%5,%6,%7}, {%8,%9}, {%0,%1,%2,%3};"
        : "+f"(d[0]), "+f"(d[1]), "+f"(d[2]), "+f"(d[3])
        : "r"(a[0]), "r"(a[1]), "r"(a[2]), "r"(a[3]), "r"(b[0]), "r"(b[1]));
}

// ---------------------------------------------------------------------------
// Merged round + k-permute pass over x, W_qkv, W_proj (one launch).
// Permuted position order within each 8-group: (k0,k4,k1,k5,k2,k6,k3,k7),
// i.e. pos(k) = 2k for k<4, 2(k-4)+1 for k>=4. Bit-identical to 3 passes.
// ---------------------------------------------------------------------------
__global__ void __launch_bounds__(256) roundperm_all(
    const float4* __restrict__ x,  float4* __restrict__ xr,
    const float4* __restrict__ w1, float4* __restrict__ w1r,
    const float4* __restrict__ w2, float4* __restrict__ w2r)
{
    int i = blockIdx.x * blockDim.x + threadIdx.x;
    const float4* in;
    float4* out;
    int j;
    if (i < NX8)              { in = x;  out = xr;  j = i; }
    else if (i < NX8 + NW18)  { in = w1; out = w1r; j = i - NX8; }
    else if (i < NALL8)       { in = w2; out = w2r; j = i - NX8 - NW18; }
    else return;

    float4 a = in[2 * j];          // k0..k3
    float4 b = in[2 * j + 1];      // k4..k7
    float4 o0, o1;
    o0.x = tf32r(a.x); o0.y = tf32r(b.x); o0.z = tf32r(a.y); o0.w = tf32r(b.y);
    o1.x = tf32r(a.z); o1.y = tf32r(b.z); o1.z = tf32r(a.w); o1.w = tf32r(b.w);
    out[2 * j]     = o0;
    out[2 * j + 1] = o1;
}

// ---------------------------------------------------------------------------
// Expand Swin rel-pos bias table -> g_bias[h][row][col]
// ---------------------------------------------------------------------------
__global__ void __launch_bounds__(256) bias_expand(const float* __restrict__ btab,
                                                   float* __restrict__ gb) {
    int i = blockIdx.x * 256 + threadIdx.x;
    int h = i >> 12;
    int rc = i & 4095;
    int row = rc >> 6, col = rc & 63;
    int yi = row >> 3, xi = row & 7;
    int yj = col >> 3, xj = col & 7;
    int idx = (yi - yj + 7) * 15 + (xi - xj + 7);
    gb[i] = btab[idx * NH + h];
}

// ---------------------------------------------------------------------------
// GEMM on k-PERMUTED operands (R15 config, best measured): C = A @ W^T + bias.
// 128x128x32, 256 thr (8 warps 2x4), warp tile 64x32.
// XOR-swizzled smem, 128B rows: u' = u ^ ((row&3)<<2) at float2 granularity
// -> conflict-free STS.128 and LDS.64 fragment loads.
// ONE barrier per ktile — prefetch distance 2 into slot (kt+2)%3
// (last read at iter kt-1, protected by this iter's barrier).
// Exact tail wait. Stage = 32KB, STAGES=3, 2 CTAs/SM.
// MODE 0: plain fp32 store. MODE 1: qkv — tf32-round + pre-scale Q cols.
// ---------------------------------------------------------------------------
#define BM 128
#define BN 128
#define BK 32
#define ROWF2 16                          // float2 units per 128B row
#define STG_A 16384                       // 128 rows x 128B
#define STG 32768                         // A + B per stage
#define STAGES 3
#define GSMEM (STAGES * STG)              // 98304 B

template<int MODE>
__global__ void __launch_bounds__(256, 2) gemm_hmma(
    const float* __restrict__ A, const float* __restrict__ W,
    const float* __restrict__ bias, float* __restrict__ C,
    int N, int K)
{
    extern __shared__ float smem[];
    const uint32_t sb = smem_u32(smem);
    const int tid  = threadIdx.x;
    const int lane = tid & 31;
    const int warp = tid >> 5;
    const int wm   = warp >> 2;
    const int wn   = warp & 3;
    const int mb   = blockIdx.y * BM;
    const int nb   = blockIdx.x * BN;

    // cp.async mapping: rows jr (+32p), 16B chunk cb, swizzled chunk
    const int jr = tid >> 3;
    const int cb = tid & 7;
    const int cbs = cb ^ ((jr & 3) << 1);          // per-thread const
    const float* Ag = A + (size_t)(mb + jr) * K + cb * 4;
    const float* Wg = W + (size_t)(nb + jr) * K + cb * 4;
    const uint32_t soff = (uint32_t)(jr * 128 + cbs * 16);

    // prologue: tiles 0,1 -> slots 0,1 (prefetch distance 2)
    #pragma unroll
    for (int s = 0; s < 2; s++) {
        const uint32_t b = sb + s * STG;
        #pragma unroll
        for (int p = 0; p < 4; p++)
            cp16(b + soff + p * 32 * 128, Ag + s * BK + (size_t)p * 32 * K);
        #pragma unroll
        for (int p = 0; p < 4; p++)
            cp16(b + STG_A + soff + p * 32 * 128, Wg + s * BK + (size_t)p * 32 * K);
        asm volatile("cp.async.commit_group;" ::: "memory");
    }

    float acc[4][4][4] = {};
    const int KT = K / BK;
    const int fr  = lane >> 2;             // fragment row within 8
    const int swz = (fr & 3) << 2;         // per-thread XOR for float2 units
    const int ub  = lane & 3;              // base float2 unit within k8 group
    const int fc2 = ub * 2;                // logical col pair base (epilogue)

    for (int kt = 0; kt < KT; kt++) {
        // youngest committed group is kt+1 (when it exists)
        if (kt + 1 < KT)
            asm volatile("cp.async.wait_group 1;" ::: "memory");
        else
            asm volatile("cp.async.wait_group 0;" ::: "memory");
        __syncthreads();   // tile kt ready for all; all warps done with iter kt-1

        // prefetch tile kt+2 into slot (kt+2)%3 (last read at iter kt-1)
        const int nk = kt + 2;
        if (nk < KT) {
            const uint32_t b = sb + (nk % STAGES) * STG;
            #pragma unroll
            for (int p = 0; p < 4; p++)
                cp16(b + soff + p * 32 * 128, Ag + nk * BK + (size_t)p * 32 * K);
            #pragma unroll
            for (int p = 0; p < 4; p++)
                cp16(b + STG_A + soff + p * 32 * 128, Wg + nk * BK + (size_t)p * 32 * K);
            asm volatile("cp.async.commit_group;" ::: "memory");
        }

        const int buf = kt % STAGES;
        const float2* Ab2 = (const float2*)(smem + buf * (STG / 4)) + (wm * 64) * ROWF2;
        const float2* Bb2 = (const float2*)(smem + buf * (STG / 4) + (STG_A / 4)) + (wn * 32) * ROWF2;

        #pragma unroll
        for (int ks = 0; ks < 4; ks++) {
            const int up = (ks * 4 + ub) ^ swz;    // swizzled float2 unit
            uint32_t afr[4][4], bfr[4][2];
            #pragma unroll
            for (int mi = 0; mi < 4; mi++) {
                float2 v0 = Ab2[(mi * 16 + fr) * ROWF2 + up];
                float2 v1 = Ab2[(mi * 16 + fr + 8) * ROWF2 + up];
                afr[mi][0] = __float_as_uint(v0.x);
                afr[mi][1] = __float_as_uint(v1.x);
                afr[mi][2] = __float_as_uint(v0.y);
                afr[mi][3] = __float_as_uint(v1.y);
            }
            #pragma unroll
            for (int ni = 0; ni < 4; ni++) {
                float2 w = Bb2[(ni * 8 + fr) * ROWF2 + up];
                bfr[ni][0] = __float_as_uint(w.x);
                bfr[ni][1] = __float_as_uint(w.y);
            }
            #pragma unroll
            for (int mi = 0; mi < 4; mi++)
                #pragma unroll
                for (int ni = 0; ni < 4; ni++)
                    mma_tf32(acc[mi][ni], afr[mi], bfr[ni]);
        }
    }

    #pragma unroll
    for (int mi = 0; mi < 4; mi++) {
        const int row = mb + wm * 64 + mi * 16 + fr;
        #pragma unroll
        for (int ni = 0; ni < 4; ni++) {
            const int col = nb + wn * 32 + ni * 8 + fc2;
            const float b0 = __ldg(bias + col), b1 = __ldg(bias + col + 1);
            float* Cp = C + (size_t)row * N + col;
            float v0 = acc[mi][ni][0] + b0, v1 = acc[mi][ni][1] + b1;
            float v2 = acc[mi][ni][2] + b0, v3 = acc[mi][ni][3] + b1;
            if (MODE == 1) {
                const float s = (col < DIM) ? SCALE : 1.0f;   // Q pre-scale
                v0 = tf32r(v0 * s); v1 = tf32r(v1 * s);
                v2 = tf32r(v2 * s); v3 = tf32r(v3 * s);
            }
            *(float2*)Cp = make_float2(v0, v1);
            *(float2*)(Cp + (size_t)8 * N) = make_float2(v2, v3);
        }
    }
}

// ---------------------------------------------------------------------------
// Attention (R8 core): one (b,h) per block, 128 threads, pure cp.async loads,
// V in [m][40], register softmax, P aliases Qs/Ks.
// Output stores k-PERMUTED (feeds proj GEMM's LDS.64 fragment path).
// ---------------------------------------------------------------------------
#define QK_ROWB 144                       // 36 floats
#define V_ROWB  160                       // 40 floats

__global__ void __launch_bounds__(128, 6) attn_kernel(
    const float* __restrict__ qkv, const float* __restrict__ gbias,
    float* __restrict__ out)
{
    __shared__ float sm[2 * 64 * 36];          // Qs | Ks; later aliased by P
    __shared__ float Vs[64][40];
    float (*Qs)[36] = (float(*)[36])sm;
    float (*Ks)[36] = (float(*)[36])(sm + 64 * 36);
    float (*P)[68]  = (float(*)[68])sm;

    const int bh = blockIdx.x;
    const int b = bh >> 4;
    const int h = bh & 15;
    const int tid = threadIdx.x;
    const int lane = tid & 31;
    const int warp = tid >> 5;

    const float* base = qkv + (size_t)b * NTOK * QKVCOLS + h * HD;
    const uint32_t sq = smem_u32(sm);
    const uint32_t sv = smem_u32(Vs);

    #pragma unroll
    for (int p = 0; p < 4; p++) {
        const int t = tid + p * 128;
        const int row = t >> 3, c = t & 7;
        const float* g = base + (size_t)row * QKVCOLS + c * 4;
        cp16(sq + row * QK_ROWB + c * 16, g);                        // Q
        cp16(sq + 64 * QK_ROWB + row * QK_ROWB + c * 16, g + DIM);   // K
        cp16(sv + row * V_ROWB + c * 16, g + 2 * DIM);               // V
    }
    asm volatile("cp.async.commit_group;" ::: "memory");
    asm volatile("cp.async.wait_group 0;" ::: "memory");
    __syncthreads();

    float sacc[8][4] = {};
    #pragma unroll
    for (int ks = 0; ks < 4; ks++) {
        const int k8 = ks * 8;
        uint32_t af[4];
        const float* p = &Qs[warp * 16 + (lane >> 2)][k8 + (lane & 3)];
        af[0] = __float_as_uint(p[0]);
        af[1] = __float_as_uint(p[8 * 36]);
        af[2] = __float_as_uint(p[4]);
        af[3] = __float_as_uint(p[8 * 36 + 4]);
        #pragma unroll
        for (int ni = 0; ni < 8; ni++) {
            uint32_t bf[2];
            const float* q = &Ks[ni * 8 + (lane >> 2)][k8 + (lane & 3)];
            bf[0] = __float_as_uint(q[0]);
            bf[1] = __float_as_uint(q[4]);
            mma_tf32(sacc[ni], af, bf);
        }
    }

    const int rA = warp * 16 + (lane >> 2);
    const int c0 = (lane & 3) * 2;
    {
        const float* gb = gbias + h * (NTOK * NTOK);
        #pragma unroll
        for (int ni = 0; ni < 8; ni++) {
            const int col = ni * 8 + c0;
            float2 b0 = *(const float2*)(gb + rA * 64 + col);
            float2 b1 = *(const float2*)(gb + (rA + 8) * 64 + col);
            sacc[ni][0] += b0.x; sacc[ni][1] += b0.y;
            sacc[ni][2] += b1.x; sacc[ni][3] += b1.y;
        }
    }
    float mx0 = -1e30f, mx1 = -1e30f;
    #pragma unroll
    for (int ni = 0; ni < 8; ni++) {
        mx0 = fmaxf(mx0, fmaxf(sacc[ni][0], sacc[ni][1]));
        mx1 = fmaxf(mx1, fmaxf(sacc[ni][2], sacc[ni][3]));
    }
    mx0 = fmaxf(mx0, __shfl_xor_sync(0xffffffffu, mx0, 1));
    mx0 = fmaxf(mx0, __shfl_xor_sync(0xffffffffu, mx0, 2));
    mx1 = fmaxf(mx1, __shfl_xor_sync(0xffffffffu, mx1, 1));
    mx1 = fmaxf(mx1, __shfl_xor_sync(0xffffffffu, mx1, 2));

    float sum0 = 0.f, sum1 = 0.f;
    #pragma unroll
    for (int ni = 0; ni < 8; ni++) {
        sacc[ni][0] = __expf(sacc[ni][0] - mx0);
        sacc[ni][1] = __expf(sacc[ni][1] - mx0);
        sacc[ni][2] = __expf(sacc[ni][2] - mx1);
        sacc[ni][3] = __expf(sacc[ni][3] - mx1);
        sum0 += sacc[ni][0] + sacc[ni][1];
        sum1 += sacc[ni][2] + sacc[ni][3];
    }
    sum0 += __shfl_xor_sync(0xffffffffu, sum0, 1);
    sum0 += __shfl_xor_sync(0xffffffffu, sum0, 2);
    sum1 += __shfl_xor_sync(0xffffffffu, sum1, 1);
    sum1 += __shfl_xor_sync(0xffffffffu, sum1, 2);
    const float inv0 = 1.f / sum0, inv1 = 1.f / sum1;

    __syncthreads();

    #pragma unroll
    for (int ni = 0; ni < 8; ni++) {
        const int col = ni * 8 + c0;
        *(float2*)(&P[rA][col]) =
            make_float2(tf32r(sacc[ni][0] * inv0), tf32r(sacc[ni][1] * inv0));
        *(float2*)(&P[rA + 8][col]) =
            make_float2(tf32r(sacc[ni][2] * inv1), tf32r(sacc[ni][3] * inv1));
    }
    __syncthreads();

    float oacc[4][4] = {};
    #pragma unroll
    for (int ks = 0; ks < 8; ks++) {
        const int k8 = ks * 8;
        uint32_t af[4];
        const float* p = &P[warp * 16 + (lane >> 2)][k8 + (lane & 3)];
        af[0] = __float_as_uint(p[0]);
        af[1] = __float_as_uint(p[8 * 68]);
        af[2] = __float_as_uint(p[4]);
        af[3] = __float_as_uint(p[8 * 68 + 4]);
        #pragma unroll
        for (int ni = 0; ni < 4; ni++) {
            uint32_t bf[2];
            const float* q = &Vs[k8 + (lane & 3)][ni * 8 + (lane >> 2)];
            bf[0] = __float_as_uint(q[0]);
            bf[1] = __float_as_uint(q[4 * 40]);
            mma_tf32(oacc[ni], af, bf);
        }
    }
    {
        // k-permuted stores: pos(c)=2c (c<4), 2(c-4)+1 (c>=4)
        const int pos_lo = (c0 < 4) ? (2 * c0) : (2 * (c0 - 4) + 1);
        const int pos_hi = (c0 + 1 < 4) ? (2 * (c0 + 1)) : (2 * (c0 - 3) + 1);
        float* ob = out + (size_t)b * NTOK * DIM + h * HD;
        #pragma unroll
        for (int ni = 0; ni < 4; ni++) {
            const int cbse = ni * 8;
            ob[(size_t)rA * DIM + cbse + pos_lo] = tf32r(oacc[ni][0]);
            ob[(size_t)rA * DIM + cbse + pos_hi] = tf32r(oacc[ni][1]);
            ob[(size_t)(rA + 8) * DIM + cbse + pos_lo] = tf32r(oacc[ni][2]);
            ob[(size_t)(rA + 8) * DIM + cbse + pos_hi] = tf32r(oacc[ni][3]);
        }
    }
}

// ---------------------------------------------------------------------------
extern "C" void kernel_launch(void* const* d_in, const int* in_sizes, int n_in,
                              void* d_out, int out_size)
{
    const float* x     = (const float*)d_in[0];
    const float* Wqkv  = (const float*)d_in[1];
    const float* bqkv  = (const float*)d_in[2];
    const float* Wproj = (const float*)d_in[3];
    const float* bproj = (const float*)d_in[4];
    const float* btab  = (const float*)d_in[5];
    float* out = (float*)d_out;

    float *qkvbuf, *attnbuf, *xr, *wqkvr, *wprojr, *gbias;
    cudaGetSymbolAddress((void**)&qkvbuf, g_qkv);
    cudaGetSymbolAddress((void**)&attnbuf, g_attn);
    cudaGetSymbolAddress((void**)&xr, g_xr);
    cudaGetSymbolAddress((void**)&wqkvr, g_wqkv);
    cudaGetSymbolAddress((void**)&wprojr, g_wproj);
    cudaGetSymbolAddress((void**)&gbias, g_bias);

    cudaFuncSetAttribute(gemm_hmma<1>, cudaFuncAttributeMaxDynamicSharedMemorySize, GSMEM);
    cudaFuncSetAttribute(gemm_hmma<0>, cudaFuncAttributeMaxDynamicSharedMemorySize, GSMEM);

    // 0) merged round + k-permute (x, W_qkv, W_proj in one launch); bias expand
    roundperm_all<<<(NALL8 + 255) / 256, 256>>>(
        (const float4*)x, (float4*)xr,
        (const float4*)Wqkv, (float4*)wqkvr,
        (const float4*)Wproj, (float4*)wprojr);
    bias_expand<<<NH * NTOK * NTOK / 256, 256>>>(btab, gbias);

    // 1) QKV projection (permuted operands; epilogue rounds + pre-scales Q; normal output)
    gemm_hmma<1><<<dim3(QKVCOLS / BN, MROWS / BM), 256, GSMEM>>>(
        xr, wqkvr, bqkv, qkvbuf, QKVCOLS, DIM);

    // 2) Windowed attention per (b, h); writes permuted g_attn
    attn_kernel<<<BATCH * NH, 128>>>(qkvbuf, gbias, attnbuf);

    // 3) Output projection (permuted operands; normal output)
    gemm_hmma<0><<<dim3(DIM / BN, MROWS / BM), 256, GSMEM>>>(
        attnbuf, wprojr, bproj, out, DIM, DIM);
}

// round 17
// speedup vs baseline: 1.0762x; 1.0017x over previous
#include <cuda_runtime.h>
#include <cstdint>

// Problem constants
#define BATCH   2048
#define NTOK    64
#define DIM     512
#define NH      16
#define HD      32
#define MROWS   (BATCH * NTOK)      // 131072
#define QKVCOLS (3 * DIM)           // 1536
#define SCALE   0.17677669529663687f // 32^-0.5

// 8-float group counts for the merged pre-pass
#define NX8   (MROWS * DIM / 8)        // 8388608
#define NW18  (QKVCOLS * DIM / 8)      // 98304
#define NW28  (DIM * DIM / 8)          // 32768
#define NALL8 (NX8 + NW18 + NW28)

// Scratch (allocation-free: __device__ globals)
__device__ float g_qkv[(size_t)MROWS * QKVCOLS];   // [B*N, 1536] rounded, Q pre-scaled, NORMAL layout
__device__ float g_attn[(size_t)MROWS * DIM];      // [B*N, 512] tf32-rounded, PERMUTED k-layout
__device__ float g_xr[(size_t)MROWS * DIM];        // tf32-rounded x (PERMUTED)
__device__ float g_wqkv[(size_t)QKVCOLS * DIM];    // tf32-rounded W_qkv (PERMUTED)
__device__ float g_wproj[(size_t)DIM * DIM];       // tf32-rounded W_proj (PERMUTED)
__device__ float g_bias[NH * NTOK * NTOK];         // expanded rel-pos bias

__device__ __forceinline__ float tf32r(float x) {
    float y;
    asm("cvt.rna.tf32.f32 %0, %1;" : "=f"(y) : "f"(x));
    return y;
}

__device__ __forceinline__ uint32_t smem_u32(const void* p) {
    uint32_t a;
    asm("{ .reg .u64 t; cvta.to.shared.u64 t, %1; cvt.u32.u64 %0, t; }" : "=r"(a) : "l"(p));
    return a;
}

__device__ __forceinline__ void cp16(uint32_t s, const void* g) {
    asm volatile("cp.async.cg.shared.global [%0], [%1], 16;" :: "r"(s), "l"(g));
}

__device__ __forceinline__ void mma_tf32(float* d, const uint32_t* a, const uint32_t* b) {
    asm volatile(
        "mma.sync.aligned.m16n8k8.row.col.f32.tf32.tf32.f32 "
        "{%0,%1,%2,%3}, {%4,%5,%6,%7}, {%8,%9}, {%0,%1,%2,%3};"
        : "+f"(d[0]), "+f"(d[1]), "+f"(d[2]), "+f"(d[3])
        : "r"(a[0]), "r"(a[1]), "r"(a[2]), "r"(a[3]), "r"(b[0]), "r"(b[1]));
}

// ---------------------------------------------------------------------------
// Merged round + k-permute pass over x, W_qkv, W_proj (one launch).
// Permuted position order within each 8-group: (k0,k4,k1,k5,k2,k6,k3,k7),
// i.e. pos(k) = 2k for k<4, 2(k-4)+1 for k>=4. Bit-identical to 3 passes.
// ---------------------------------------------------------------------------
__global__ void __launch_bounds__(256) roundperm_all(
    const float4* __restrict__ x,  float4* __restrict__ xr,
    const float4* __restrict__ w1, float4* __restrict__ w1r,
    const float4* __restrict__ w2, float4* __restrict__ w2r)
{
    int i = blockIdx.x * blockDim.x + threadIdx.x;
    const float4* in;
    float4* out;
    int j;
    if (i < NX8)              { in = x;  out = xr;  j = i; }
    else if (i < NX8 + NW18)  { in = w1; out = w1r; j = i - NX8; }
    else if (i < NALL8)       { in = w2; out = w2r; j = i - NX8 - NW18; }
    else return;

    float4 a = in[2 * j];          // k0..k3
    float4 b = in[2 * j + 1];      // k4..k7
    float4 o0, o1;
    o0.x = tf32r(a.x); o0.y = tf32r(b.x); o0.z = tf32r(a.y); o0.w = tf32r(b.y);
    o1.x = tf32r(a.z); o1.y = tf32r(b.z); o1.z = tf32r(a.w); o1.w = tf32r(b.w);
    out[2 * j]     = o0;
    out[2 * j + 1] = o1;
}

// ---------------------------------------------------------------------------
// Expand Swin rel-pos bias table -> g_bias[h][row][col]
// ---------------------------------------------------------------------------
__global__ void __launch_bounds__(256) bias_expand(const float* __restrict__ btab,
                                                   float* __restrict__ gb) {
    int i = blockIdx.x * 256 + threadIdx.x;
    int h = i >> 12;
    int rc = i & 4095;
    int row = rc >> 6, col = rc & 63;
    int yi = row >> 3, xi = row & 7;
    int yj = col >> 3, xj = col & 7;
    int idx = (yi - yj + 7) * 15 + (xi - xj + 7);
    gb[i] = btab[idx * NH + h];
}

// ---------------------------------------------------------------------------
// GEMM on k-PERMUTED operands (R15 config, best measured): C = A @ W^T + bias.
// 128x128x32, 256 thr (8 warps 2x4), warp tile 64x32.
// XOR-swizzled smem, 128B rows: u' = u ^ ((row&3)<<2) at float2 granularity
// -> conflict-free STS.128 and LDS.64 fragment loads.
// ONE barrier per ktile — prefetch distance 2 into slot (kt+2)%3
// (last read at iter kt-1, protected by this iter's barrier).
// Exact tail wait. Stage = 32KB, STAGES=3, 2 CTAs/SM.
// MODE 0: plain fp32 store. MODE 1: qkv — tf32-round + pre-scale Q cols.
// ---------------------------------------------------------------------------
#define BM 128
#define BN 128
#define BK 32
#define ROWF2 16                          // float2 units per 128B row
#define STG_A 16384                       // 128 rows x 128B
#define STG 32768                         // A + B per stage
#define STAGES 3
#define GSMEM (STAGES * STG)              // 98304 B

template<int MODE>
__global__ void __launch_bounds__(256, 2) gemm_hmma(
    const float* __restrict__ A, const float* __restrict__ W,
    const float* __restrict__ bias, float* __restrict__ C,
    int N, int K)
{
    extern __shared__ float smem[];
    const uint32_t sb = smem_u32(smem);
    const int tid  = threadIdx.x;
    const int lane = tid & 31;
    const int warp = tid >> 5;
    const int wm   = warp >> 2;
    const int wn   = warp & 3;
    const int mb   = blockIdx.y * BM;
    const int nb   = blockIdx.x * BN;

    // cp.async mapping: rows jr (+32p), 16B chunk cb, swizzled chunk
    const int jr = tid >> 3;
    const int cb = tid & 7;
    const int cbs = cb ^ ((jr & 3) << 1);          // per-thread const
    const float* Ag = A + (size_t)(mb + jr) * K + cb * 4;
    const float* Wg = W + (size_t)(nb + jr) * K + cb * 4;
    const uint32_t soff = (uint32_t)(jr * 128 + cbs * 16);

    // prologue: tiles 0,1 -> slots 0,1 (prefetch distance 2)
    #pragma unroll
    for (int s = 0; s < 2; s++) {
        const uint32_t b = sb + s * STG;
        #pragma unroll
        for (int p = 0; p < 4; p++)
            cp16(b + soff + p * 32 * 128, Ag + s * BK + (size_t)p * 32 * K);
        #pragma unroll
        for (int p = 0; p < 4; p++)
            cp16(b + STG_A + soff + p * 32 * 128, Wg + s * BK + (size_t)p * 32 * K);
        asm volatile("cp.async.commit_group;" ::: "memory");
    }

    float acc[4][4][4] = {};
    const int KT = K / BK;
    const int fr  = lane >> 2;             // fragment row within 8
    const int swz = (fr & 3) << 2;         // per-thread XOR for float2 units
    const int ub  = lane & 3;              // base float2 unit within k8 group
    const int fc2 = ub * 2;                // logical col pair base (epilogue)

    for (int kt = 0; kt < KT; kt++) {
        // youngest committed group is kt+1 (when it exists)
        if (kt + 1 < KT)
            asm volatile("cp.async.wait_group 1;" ::: "memory");
        else
            asm volatile("cp.async.wait_group 0;" ::: "memory");
        __syncthreads();   // tile kt ready for all; all warps done with iter kt-1

        // prefetch tile kt+2 into slot (kt+2)%3 (last read at iter kt-1)
        const int nk = kt + 2;
        if (nk < KT) {
            const uint32_t b = sb + (nk % STAGES) * STG;
            #pragma unroll
            for (int p = 0; p < 4; p++)
                cp16(b + soff + p * 32 * 128, Ag + nk * BK + (size_t)p * 32 * K);
            #pragma unroll
            for (int p = 0; p < 4; p++)
                cp16(b + STG_A + soff + p * 32 * 128, Wg + nk * BK + (size_t)p * 32 * K);
            asm volatile("cp.async.commit_group;" ::: "memory");
        }

        const int buf = kt % STAGES;
        const float2* Ab2 = (const float2*)(smem + buf * (STG / 4)) + (wm * 64) * ROWF2;
        const float2* Bb2 = (const float2*)(smem + buf * (STG / 4) + (STG_A / 4)) + (wn * 32) * ROWF2;

        #pragma unroll
        for (int ks = 0; ks < 4; ks++) {
            const int up = (ks * 4 + ub) ^ swz;    // swizzled float2 unit
            uint32_t afr[4][4], bfr[4][2];
            #pragma unroll
            for (int mi = 0; mi < 4; mi++) {
                float2 v0 = Ab2[(mi * 16 + fr) * ROWF2 + up];
                float2 v1 = Ab2[(mi * 16 + fr + 8) * ROWF2 + up];
                afr[mi][0] = __float_as_uint(v0.x);
                afr[mi][1] = __float_as_uint(v1.x);
                afr[mi][2] = __float_as_uint(v0.y);
                afr[mi][3] = __float_as_uint(v1.y);
            }
            #pragma unroll
            for (int ni = 0; ni < 4; ni++) {
                float2 w = Bb2[(ni * 8 + fr) * ROWF2 + up];
                bfr[ni][0] = __float_as_uint(w.x);
                bfr[ni][1] = __float_as_uint(w.y);
            }
            #pragma unroll
            for (int mi = 0; mi < 4; mi++)
                #pragma unroll
                for (int ni = 0; ni < 4; ni++)
                    mma_tf32(acc[mi][ni], afr[mi], bfr[ni]);
        }
    }

    #pragma unroll
    for (int mi = 0; mi < 4; mi++) {
        const int row = mb + wm * 64 + mi * 16 + fr;
        #pragma unroll
        for (int ni = 0; ni < 4; ni++) {
            const int col = nb + wn * 32 + ni * 8 + fc2;
            const float b0 = __ldg(bias + col), b1 = __ldg(bias + col + 1);
            float* Cp = C + (size_t)row * N + col;
            float v0 = acc[mi][ni][0] + b0, v1 = acc[mi][ni][1] + b1;
            float v2 = acc[mi][ni][2] + b0, v3 = acc[mi][ni][3] + b1;
            if (MODE == 1) {
                const float s = (col < DIM) ? SCALE : 1.0f;   // Q pre-scale
                v0 = tf32r(v0 * s); v1 = tf32r(v1 * s);
                v2 = tf32r(v2 * s); v3 = tf32r(v3 * s);
            }
            *(float2*)Cp = make_float2(v0, v1);
            *(float2*)(Cp + (size_t)8 * N) = make_float2(v2, v3);
        }
    }
}

// ---------------------------------------------------------------------------
// Attention (R8 core): one (b,h) per block, 128 threads, pure cp.async loads,
// V in [m][40], register softmax, P aliases Qs/Ks.
// Output stores k-PERMUTED (feeds proj GEMM's LDS.64 fragment path).
// ---------------------------------------------------------------------------
#define QK_ROWB 144                       // 36 floats
#define V_ROWB  160                       // 40 floats

__global__ void __launch_bounds__(128, 6) attn_kernel(
    const float* __restrict__ qkv, const float* __restrict__ gbias,
    float* __restrict__ out)
{
    __shared__ float sm[2 * 64 * 36];          // Qs | Ks; later aliased by P
    __shared__ float Vs[64][40];
    float (*Qs)[36] = (float(*)[36])sm;
    float (*Ks)[36] = (float(*)[36])(sm + 64 * 36);
    float (*P)[68]  = (float(*)[68])sm;

    const int bh = blockIdx.x;
    const int b = bh >> 4;
    const int h = bh & 15;
    const int tid = threadIdx.x;
    const int lane = tid & 31;
    const int warp = tid >> 5;

    const float* base = qkv + (size_t)b * NTOK * QKVCOLS + h * HD;
    const uint32_t sq = smem_u32(sm);
    const uint32_t sv = smem_u32(Vs);

    #pragma unroll
    for (int p = 0; p < 4; p++) {
        const int t = tid + p * 128;
        const int row = t >> 3, c = t & 7;
        const float* g = base + (size_t)row * QKVCOLS + c * 4;
        cp16(sq + row * QK_ROWB + c * 16, g);                        // Q
        cp16(sq + 64 * QK_ROWB + row * QK_ROWB + c * 16, g + DIM);   // K
        cp16(sv + row * V_ROWB + c * 16, g + 2 * DIM);               // V
    }
    asm volatile("cp.async.commit_group;" ::: "memory");
    asm volatile("cp.async.wait_group 0;" ::: "memory");
    __syncthreads();

    float sacc[8][4] = {};
    #pragma unroll
    for (int ks = 0; ks < 4; ks++) {
        const int k8 = ks * 8;
        uint32_t af[4];
        const float* p = &Qs[warp * 16 + (lane >> 2)][k8 + (lane & 3)];
        af[0] = __float_as_uint(p[0]);
        af[1] = __float_as_uint(p[8 * 36]);
        af[2] = __float_as_uint(p[4]);
        af[3] = __float_as_uint(p[8 * 36 + 4]);
        #pragma unroll
        for (int ni = 0; ni < 8; ni++) {
            uint32_t bf[2];
            const float* q = &Ks[ni * 8 + (lane >> 2)][k8 + (lane & 3)];
            bf[0] = __float_as_uint(q[0]);
            bf[1] = __float_as_uint(q[4]);
            mma_tf32(sacc[ni], af, bf);
        }
    }

    const int rA = warp * 16 + (lane >> 2);
    const int c0 = (lane & 3) * 2;
    {
        const float* gb = gbias + h * (NTOK * NTOK);
        #pragma unroll
        for (int ni = 0; ni < 8; ni++) {
            const int col = ni * 8 + c0;
            float2 b0 = *(const float2*)(gb + rA * 64 + col);
            float2 b1 = *(const float2*)(gb + (rA + 8) * 64 + col);
            sacc[ni][0] += b0.x; sacc[ni][1] += b0.y;
            sacc[ni][2] += b1.x; sacc[ni][3] += b1.y;
        }
    }
    float mx0 = -1e30f, mx1 = -1e30f;
    #pragma unroll
    for (int ni = 0; ni < 8; ni++) {
        mx0 = fmaxf(mx0, fmaxf(sacc[ni][0], sacc[ni][1]));
        mx1 = fmaxf(mx1, fmaxf(sacc[ni][2], sacc[ni][3]));
    }
    mx0 = fmaxf(mx0, __shfl_xor_sync(0xffffffffu, mx0, 1));
    mx0 = fmaxf(mx0, __shfl_xor_sync(0xffffffffu, mx0, 2));
    mx1 = fmaxf(mx1, __shfl_xor_sync(0xffffffffu, mx1, 1));
    mx1 = fmaxf(mx1, __shfl_xor_sync(0xffffffffu, mx1, 2));

    float sum0 = 0.f, sum1 = 0.f;
    #pragma unroll
    for (int ni = 0; ni < 8; ni++) {
        sacc[ni][0] = __expf(sacc[ni][0] - mx0);
        sacc[ni][1] = __expf(sacc[ni][1] - mx0);
        sacc[ni][2] = __expf(sacc[ni][2] - mx1);
        sacc[ni][3] = __expf(sacc[ni][3] - mx1);
        sum0 += sacc[ni][0] + sacc[ni][1];
        sum1 += sacc[ni][2] + sacc[ni][3];
    }
    sum0 += __shfl_xor_sync(0xffffffffu, sum0, 1);
    sum0 += __shfl_xor_sync(0xffffffffu, sum0, 2);
    sum1 += __shfl_xor_sync(0xffffffffu, sum1, 1);
    sum1 += __shfl_xor_sync(0xffffffffu, sum1, 2);
    const float inv0 = 1.f / sum0, inv1 = 1.f / sum1;

    __syncthreads();

    #pragma unroll
    for (int ni = 0; ni < 8; ni++) {
        const int col = ni * 8 + c0;
        *(float2*)(&P[rA][col]) =
            make_float2(tf32r(sacc[ni][0] * inv0), tf32r(sacc[ni][1] * inv0));
        *(float2*)(&P[rA + 8][col]) =
            make_float2(tf32r(sacc[ni][2] * inv1), tf32r(sacc[ni][3] * inv1));
    }
    __syncthreads();

    float oacc[4][4] = {};
    #pragma unroll
    for (int ks = 0; ks < 8; ks++) {
        const int k8 = ks * 8;
        uint32_t af[4];
        const float* p = &P[warp * 16 + (lane >> 2)][k8 + (lane & 3)];
        af[0] = __float_as_uint(p[0]);
        af[1] = __float_as_uint(p[8 * 68]);
        af[2] = __float_as_uint(p[4]);
        af[3] = __float_as_uint(p[8 * 68 + 4]);
        #pragma unroll
        for (int ni = 0; ni < 4; ni++) {
            uint32_t bf[2];
            const float* q = &Vs[k8 + (lane & 3)][ni * 8 + (lane >> 2)];
            bf[0] = __float_as_uint(q[0]);
            bf[1] = __float_as_uint(q[4 * 40]);
            mma_tf32(oacc[ni], af, bf);
        }
    }
    {
        // k-permuted stores: pos(c)=2c (c<4), 2(c-4)+1 (c>=4)
        const int pos_lo = (c0 < 4) ? (2 * c0) : (2 * (c0 - 4) + 1);
        const int pos_hi = (c0 + 1 < 4) ? (2 * (c0 + 1)) : (2 * (c0 - 3) + 1);
        float* ob = out + (size_t)b * NTOK * DIM + h * HD;
        #pragma unroll
        for (int ni = 0; ni < 4; ni++) {
            const int cbse = ni * 8;
            ob[(size_t)rA * DIM + cbse + pos_lo] = tf32r(oacc[ni][0]);
            ob[(size_t)rA * DIM + cbse + pos_hi] = tf32r(oacc[ni][1]);
            ob[(size_t)(rA + 8) * DIM + cbse + pos_lo] = tf32r(oacc[ni][2]);
            ob[(size_t)(rA + 8) * DIM + cbse + pos_hi] = tf32r(oacc[ni][3]);
        }
    }
}

// ---------------------------------------------------------------------------
extern "C" void kernel_launch(void* const* d_in, const int* in_sizes, int n_in,
                              void* d_out, int out_size)
{
    const float* x     = (const float*)d_in[0];
    const float* Wqkv  = (const float*)d_in[1];
    const float* bqkv  = (const float*)d_in[2];
    const float* Wproj = (const float*)d_in[3];
    const float* bproj = (const float*)d_in[4];
    const float* btab  = (const float*)d_in[5];
    float* out = (float*)d_out;

    float *qkvbuf, *attnbuf, *xr, *wqkvr, *wprojr, *gbias;
    cudaGetSymbolAddress((void**)&qkvbuf, g_qkv);
    cudaGetSymbolAddress((void**)&attnbuf, g_attn);
    cudaGetSymbolAddress((void**)&xr, g_xr);
    cudaGetSymbolAddress((void**)&wqkvr, g_wqkv);
    cudaGetSymbolAddress((void**)&wprojr, g_wproj);
    cudaGetSymbolAddress((void**)&gbias, g_bias);

    cudaFuncSetAttribute(gemm_hmma<1>, cudaFuncAttributeMaxDynamicSharedMemorySize, GSMEM);
    cudaFuncSetAttribute(gemm_hmma<0>, cudaFuncAttributeMaxDynamicSharedMemorySize, GSMEM);

    // 0) merged round + k-permute (x, W_qkv, W_proj in one launch); bias expand
    roundperm_all<<<(NALL8 + 255) / 256, 256>>>(
        (const float4*)x, (float4*)xr,
        (const float4*)Wqkv, (float4*)wqkvr,
        (const float4*)Wproj, (float4*)wprojr);
    bias_expand<<<NH * NTOK * NTOK / 256, 256>>>(btab, gbias);

    // 1) QKV projection (permuted operands; epilogue rounds + pre-scales Q; normal output)
    gemm_hmma<1><<<dim3(QKVCOLS / BN, MROWS / BM), 256, GSMEM>>>(
        xr, wqkvr, bqkv, qkvbuf, QKVCOLS, DIM);

    // 2) Windowed attention per (b, h); writes permuted g_attn
    attn_kernel<<<BATCH * NH, 128>>>(qkvbuf, gbias, attnbuf);

    // 3) Output projection (permuted operands; normal output)
    gemm_hmma<0><<<dim3(DIM / BN, MROWS / BM), 256, GSMEM>>>(
        attnbuf, wprojr, bproj, out, DIM, DIM);
}